// round 9
// baseline (speedup 1.0000x reference)
#include <cuda_runtime.h>
#include <cstdint>

#define BATCH 8
#define HH    64
#define WW_   64
#define TT    4096
#define CC    256
#define DD    512
#define MM    (BATCH * TT)   // 32768

#define NCHAIN 4096
#define NCHUNK 32
#define CHLEN  128

// ---------------- scratch (static device globals; no runtime alloc) ----------
__device__ float g_comb[25 * CC];
__device__ float g_xf[BATCH * TT * CC];     // tf32-rounded activations
__device__ float g_k [BATCH * TT * CC];
__device__ float g_v [BATCH * TT * CC];
__device__ float g_sr[BATCH * TT * CC];
__device__ float g_xs[BATCH * TT * DD];     // tf32-rounded scan output
__device__ float g_sa[NCHUNK * NCHAIN];
__device__ float g_sb[NCHUNK * NCHAIN];
__device__ float g_sp[NCHUNK * NCHAIN];
__device__ float g_pa[NCHUNK * NCHAIN];
__device__ float g_pb[NCHUNK * NCHAIN];
__device__ float g_pp[NCHUNK * NCHAIN];
// tf32-rounded weights
__device__ float g_wk[CC * CC];
__device__ float g_wv[CC * CC];
__device__ float g_wr[CC * CC];
__device__ float g_wo[CC * DD];

__device__ __forceinline__ unsigned f2tf32(float f) {
    unsigned u;
    asm("cvt.rna.tf32.f32 %0, %1;" : "=r"(u) : "f"(f));
    return u;
}
__device__ __forceinline__ float rnd_tf32(float f) {
    return __uint_as_float(f2tf32(f));
}
__device__ __forceinline__ uint32_t smem_u32(const void* p) {
    uint32_t a;
    asm("{ .reg .u64 t; cvta.to.shared.u64 t, %1; cvt.u32.u64 %0, t; }"
        : "=r"(a) : "l"(p));
    return a;
}
__device__ __forceinline__ void cp16(uint32_t dst, const void* src) {
    asm volatile("cp.async.ca.shared.global [%0], [%1], 16;" :: "r"(dst), "l"(src));
}
#define CP_COMMIT() asm volatile("cp.async.commit_group;" ::: "memory")
#define CP_WAIT1()  asm volatile("cp.async.wait_group 1;"  ::: "memory")

// ---------------- 0) round weights to tf32 grid (one cheap launch) -----------
__global__ void round_weights_kernel(const float* __restrict__ Wk,
                                     const float* __restrict__ Wv,
                                     const float* __restrict__ Wr,
                                     const float* __restrict__ Wo)
{
    int i = blockIdx.x * 256 + threadIdx.x;
    if (i < CC * CC) {
        g_wk[i] = rnd_tf32(Wk[i]);
        g_wv[i] = rnd_tf32(Wv[i]);
        g_wr[i] = rnd_tf32(Wr[i]);
    }
    if (i < CC * DD) g_wo[i] = rnd_tf32(Wo[i]);
}

// ---------------- 1) combine identity + 1x1 + 3x3 + 5x5 into one 5x5 ---------
__global__ void combine_weights_kernel(const float* __restrict__ alpha,
                                       const float* __restrict__ cw1,
                                       const float* __restrict__ cw3,
                                       const float* __restrict__ cw5)
{
    int c = threadIdx.x;
    float a0 = alpha[0], a1 = alpha[1], a2 = alpha[2], a3 = alpha[3];
    #pragma unroll
    for (int j = 0; j < 5; j++) {
        #pragma unroll
        for (int i = 0; i < 5; i++) {
            float v = a3 * cw5[c * 25 + j * 5 + i];
            if (j >= 1 && j <= 3 && i >= 1 && i <= 3)
                v += a2 * cw3[c * 9 + (j - 1) * 3 + (i - 1)];
            if (j == 2 && i == 2)
                v += a1 * cw1[c] + a0;
            g_comb[(j * 5 + i) * CC + c] = v;
        }
    }
}

// ---------------- 2) depthwise 5x5 conv; output tf32-rounded -----------------
__global__ __launch_bounds__(256) void omni_conv_kernel(const float* __restrict__ x)
{
    int b  = blockIdx.x >> 6;
    int xc = blockIdx.x & 63;
    int c  = threadIdx.x;

    float wgt[25];
    #pragma unroll
    for (int j = 0; j < 25; j++) wgt[j] = g_comb[j * CC + c];

    const float* xin  = x    + (size_t)b * TT * CC + c;
    float*       xout = g_xf + (size_t)b * TT * CC + (size_t)xc * CC + c;

    float win[5][5];
    #pragma unroll
    for (int i = 0; i < 5; i++) { win[0][i] = 0.f; win[1][i] = 0.f; }
    #pragma unroll
    for (int r = 0; r < 3; r++) {
        #pragma unroll
        for (int i = 0; i < 5; i++) {
            int xx = xc - 2 + i;
            win[2 + r][i] = (xx >= 0 && xx < WW_) ? xin[((size_t)r * WW_ + xx) * CC] : 0.f;
        }
    }

    #pragma unroll 2
    for (int y = 0; y < HH; y++) {
        float acc = 0.f;
        #pragma unroll
        for (int j = 0; j < 5; j++)
            #pragma unroll
            for (int i = 0; i < 5; i++)
                acc = fmaf(wgt[j * 5 + i], win[j][i], acc);
        xout[(size_t)y * WW_ * CC] = rnd_tf32(acc);

        #pragma unroll
        for (int j = 0; j < 4; j++)
            #pragma unroll
            for (int i = 0; i < 5; i++) win[j][i] = win[j + 1][i];
        int row = y + 3;
        #pragma unroll
        for (int i = 0; i < 5; i++) {
            int xx = xc - 2 + i;
            win[4][i] = (row < HH && xx >= 0 && xx < WW_)
                        ? xin[((size_t)row * WW_ + xx) * CC] : 0.f;
        }
    }
}

// ---------------- 3) tf32 mma.sync GEMM, cp.async 3-stage pipeline -----------
// Inputs are pre-rounded to the tf32 grid, so HW truncation in mma == rna.
// Block 128x128x32, 8 warps (2x4), warp tile 64x32, m16n8k8.
// smem: unsigned [3 stages][128][36] for A and W (stride 36 = conflict-free).
#define TILE_U   (128 * 36)                 // words per stage tile
#define GS_BYTES (6 * TILE_U * 4)           // 110592 bytes

__device__ __forceinline__ void issue_tile(const float* __restrict__ src, int ldk,
                                           uint32_t smdst, int tid)
{
    int lrow = tid >> 1, lcol = (tid & 1) * 16;
    const float* p = src + (size_t)lrow * ldk + lcol;
    uint32_t d = smdst + (uint32_t)(lrow * 36 + lcol) * 4;
    cp16(d,      p);
    cp16(d + 16, p + 4);
    cp16(d + 32, p + 8);
    cp16(d + 48, p + 12);
}

__global__ __launch_bounds__(256) void gemm_qkv_kernel(
    const float* __restrict__ A,
    const float* __restrict__ W0, const float* __restrict__ W1,
    const float* __restrict__ W2,
    float* __restrict__ O0, float* __restrict__ O1, float* __restrict__ O2,
    int K, int actsel)
{
    extern __shared__ unsigned gsm[];
    const uint32_t smb = smem_u32(gsm);
    const int tid = threadIdx.x;
    const int grp = blockIdx.x >> 1;               // 0..2 selects weight/output
    const int bn  = (blockIdx.x & 1) * 128;
    const float* W   = (grp == 0) ? W0 : (grp == 1) ? W1 : W2;
    float*       Out = (grp == 0) ? O0 : (grp == 1) ? O1 : O2;
    const int act = (actsel >> grp) & 1;
    const size_t bm = (size_t)blockIdx.y * 128;

    const int lane = tid & 31, wid = tid >> 5;
    const int wm = (wid & 1) * 64;
    const int wn = (wid >> 1) * 32;
    const int qr = lane >> 2;
    const int qc = lane & 3;

    const float* Abase = A + bm * (size_t)K;
    const float* Wbase = W + (size_t)bn * K;
    const int NT = K >> 5;

    float acc[4][4][4];
    #pragma unroll
    for (int mf = 0; mf < 4; mf++)
        #pragma unroll
        for (int nf = 0; nf < 4; nf++)
            #pragma unroll
            for (int i = 0; i < 4; i++) acc[mf][nf][i] = 0.f;

    // prologue: stages 0 and 1 in flight
    issue_tile(Abase,      K, smb,                        tid);
    issue_tile(Wbase,      K, smb + 3 * TILE_U * 4,       tid);
    CP_COMMIT();
    issue_tile(Abase + 32, K, smb + TILE_U * 4,           tid);
    issue_tile(Wbase + 32, K, smb + 4 * TILE_U * 4,       tid);
    CP_COMMIT();

    for (int kt = 0; kt < NT; kt++) {
        CP_WAIT1();
        __syncthreads();

        if (kt + 2 < NT) {
            int st = (kt + 2) % 3;
            issue_tile(Abase + (kt + 2) * 32, K, smb + st * TILE_U * 4,       tid);
            issue_tile(Wbase + (kt + 2) * 32, K, smb + (3 + st) * TILE_U * 4, tid);
        }
        CP_COMMIT();

        const unsigned (*As)[36] = (const unsigned (*)[36])(gsm + (kt % 3) * TILE_U);
        const unsigned (*Ws)[36] = (const unsigned (*)[36])(gsm + (3 + kt % 3) * TILE_U);

        #pragma unroll
        for (int k8 = 0; k8 < 4; k8++) {
            const int kc = k8 * 8;
            unsigned b0[4], b1[4];
            #pragma unroll
            for (int nf = 0; nf < 4; nf++) {
                int n = wn + nf * 8 + qr;
                b0[nf] = Ws[n][kc + qc];
                b1[nf] = Ws[n][kc + qc + 4];
            }
            #pragma unroll
            for (int mf = 0; mf < 4; mf++) {
                int r0 = wm + mf * 16 + qr;
                unsigned a0 = As[r0][kc + qc];
                unsigned a1 = As[r0 + 8][kc + qc];
                unsigned a2 = As[r0][kc + qc + 4];
                unsigned a3 = As[r0 + 8][kc + qc + 4];
                #pragma unroll
                for (int nf = 0; nf < 4; nf++) {
                    asm volatile(
                        "mma.sync.aligned.m16n8k8.row.col.f32.tf32.tf32.f32 "
                        "{%0,%1,%2,%3}, {%4,%5,%6,%7}, {%8,%9}, {%0,%1,%2,%3};"
                        : "+f"(acc[mf][nf][0]), "+f"(acc[mf][nf][1]),
                          "+f"(acc[mf][nf][2]), "+f"(acc[mf][nf][3])
                        : "r"(a0), "r"(a1), "r"(a2), "r"(a3),
                          "r"(b0[nf]), "r"(b1[nf]));
                }
            }
        }
    }

    #pragma unroll
    for (int mf = 0; mf < 4; mf++) {
        size_t r0 = bm + wm + mf * 16 + qr;
        #pragma unroll
        for (int nf = 0; nf < 4; nf++) {
            int col = bn + wn + nf * 8 + qc * 2;
            float c0 = acc[mf][nf][0], c1 = acc[mf][nf][1];
            float c2 = acc[mf][nf][2], c3 = acc[mf][nf][3];
            if (act) {
                c0 = 1.0f / (1.0f + __expf(-c0));
                c1 = 1.0f / (1.0f + __expf(-c1));
                c2 = 1.0f / (1.0f + __expf(-c2));
                c3 = 1.0f / (1.0f + __expf(-c3));
            }
            *(float2*)(Out + r0 * 256 + col)       = make_float2(c0, c1);
            *(float2*)(Out + (r0 + 8) * 256 + col) = make_float2(c2, c3);
        }
    }
}

// ---------------- 4) WKV chunk-parallel scan ---------------------------------
__device__ __forceinline__ void wkv_state(float kt, float vt, float wdec,
                                          float& a, float& b, float& pp)
{
    float ww2 = pp + wdec;
    float d2  = ww2 - kt;
    float f   = __expf(-fabsf(d2));
    float f1  = (d2 >= 0.f) ? 1.f : f;
    float f2  = (d2 >= 0.f) ? f : 1.f;
    a  = f1 * a + f2 * vt;
    b  = f1 * b + f2;
    pp = fmaxf(ww2, kt);
}

__global__ __launch_bounds__(256) void wkv_pass1(const float* __restrict__ sd)
{
    int g     = blockIdx.x * 256 + threadIdx.x;
    int chain = g & (NCHAIN - 1);
    int chunk = g >> 12;
    int b = chain >> 9;
    int d = chain & 511;
    int c = d & 255;
    bool second = d >= 256;

    float wdec = -__expf(sd[d] * (1.0f / (float)TT));
    const size_t base = (size_t)b * TT * CC + c;

    float a = 0.f, bb = 0.f, pp = -1e38f;
    int tstart = chunk * CHLEN;

    for (int t0 = tstart; t0 < tstart + CHLEN; t0 += 8) {
        float kb[8], vb[8];
        #pragma unroll
        for (int i = 0; i < 8; i++) {
            int t  = t0 + i;
            int ti = second ? (((t & 63) << 6) | (t >> 6)) : t;
            size_t off = base + (size_t)ti * CC;
            kb[i] = g_k[off];
            vb[i] = g_v[off];
        }
        #pragma unroll
        for (int i = 0; i < 8; i++)
            wkv_state(kb[i], vb[i], wdec, a, bb, pp);
    }
    g_sa[chunk * NCHAIN + chain] = a;
    g_sb[chunk * NCHAIN + chain] = bb;
    g_sp[chunk * NCHAIN + chain] = pp;
}

__global__ __launch_bounds__(256) void wkv_pass2(const float* __restrict__ sd)
{
    int chain = blockIdx.x * 256 + threadIdx.x;
    int d = chain & 511;
    float wdec = -__expf(sd[d] * (1.0f / (float)TT));
    float Lw = (float)CHLEN * wdec;

    float A = 0.f, B = 0.f, P = -1e38f;
    for (int j = 0; j < NCHUNK; j++) {
        g_pa[j * NCHAIN + chain] = A;
        g_pb[j * NCHAIN + chain] = B;
        g_pp[j * NCHAIN + chain] = P;
        float ca = g_sa[j * NCHAIN + chain];
        float cb = g_sb[j * NCHAIN + chain];
        float cp = g_sp[j * NCHAIN + chain];
        float np = P + Lw;
        float p  = fmaxf(np, cp);
        float e1 = __expf(np - p);
        float e2 = __expf(cp - p);
        A = e1 * A + e2 * ca;
        B = e1 * B + e2 * cb;
        P = p;
    }
}

__global__ __launch_bounds__(256) void wkv_pass3(const float* __restrict__ sd,
                                                 const float* __restrict__ sf)
{
    int g     = blockIdx.x * 256 + threadIdx.x;
    int chain = g & (NCHAIN - 1);
    int chunk = g >> 12;
    int b = chain >> 9;
    int d = chain & 511;
    int c = d & 255;
    bool second = d >= 256;

    float wdec = -__expf(sd[d] * (1.0f / (float)TT));
    float u    =  sf[d] * (1.0f / (float)TT);

    const size_t base = (size_t)b * TT * CC + c;
    float* xsp = g_xs + (size_t)b * TT * DD + d;

    float a  = g_pa[chunk * NCHAIN + chain];
    float bb = g_pb[chunk * NCHAIN + chain];
    float pp = g_pp[chunk * NCHAIN + chain];

    int tstart = chunk * CHLEN;
    for (int t0 = tstart; t0 < tstart + CHLEN; t0 += 8) {
        float kb[8], vb[8], sb[8];
        #pragma unroll
        for (int i = 0; i < 8; i++) {
            int t  = t0 + i;
            int ti = second ? (((t & 63) << 6) | (t >> 6)) : t;
            size_t off = base + (size_t)ti * CC;
            kb[i] = g_k[off];
            vb[i] = g_v[off];
            sb[i] = g_sr[base + (size_t)t * CC];
        }
        #pragma unroll
        for (int i = 0; i < 8; i++) {
            float kt = kb[i], vt = vb[i];
            float ww = u + kt;
            float d1 = pp - ww;
            float e  = __expf(-fabsf(d1));
            float e1 = (d1 >= 0.f) ? 1.f : e;
            float e2 = (d1 >= 0.f) ? e : 1.f;
            float out = __fdividef(e1 * a + e2 * vt, e1 * bb + e2);
            wkv_state(kt, vt, wdec, a, bb, pp);
            xsp[(size_t)(t0 + i) * DD] = rnd_tf32(out * sb[i]);
        }
    }
}

// ---------------- launch -----------------------------------------------------
extern "C" void kernel_launch(void* const* d_in, const int* in_sizes, int n_in,
                              void* d_out, int out_size)
{
    const float* x     = (const float*)d_in[0];
    const float* alpha = (const float*)d_in[1];
    const float* cw1   = (const float*)d_in[2];
    const float* cw3   = (const float*)d_in[3];
    const float* cw5   = (const float*)d_in[4];
    const float* Wk    = (const float*)d_in[5];
    const float* Wv    = (const float*)d_in[6];
    const float* Wr    = (const float*)d_in[7];
    const float* Wo    = (const float*)d_in[8];
    const float* sd    = (const float*)d_in[9];
    const float* sf    = (const float*)d_in[10];

    float *xf, *k, *v, *sr, *xs, *wk, *wv, *wr, *wo;
    cudaGetSymbolAddress((void**)&xf, g_xf);
    cudaGetSymbolAddress((void**)&k,  g_k);
    cudaGetSymbolAddress((void**)&v,  g_v);
    cudaGetSymbolAddress((void**)&sr, g_sr);
    cudaGetSymbolAddress((void**)&xs, g_xs);
    cudaGetSymbolAddress((void**)&wk, g_wk);
    cudaGetSymbolAddress((void**)&wv, g_wv);
    cudaGetSymbolAddress((void**)&wr, g_wr);
    cudaGetSymbolAddress((void**)&wo, g_wo);

    cudaFuncSetAttribute(gemm_qkv_kernel,
                         cudaFuncAttributeMaxDynamicSharedMemorySize, GS_BYTES);

    round_weights_kernel<<<(CC * DD + 255) / 256, 256>>>(Wk, Wv, Wr, Wo);
    combine_weights_kernel<<<1, 256>>>(alpha, cw1, cw3, cw5);
    omni_conv_kernel<<<BATCH * WW_, 256>>>(x);

    // fused k / v / r(sigmoid) gemms: grid.x = 6 (3 groups x 2 n-blocks)
    dim3 g3(6, MM / 128);
    gemm_qkv_kernel<<<g3, 256, GS_BYTES>>>(xf, wk, wv, wr, k, v, sr, CC, 4);

    wkv_pass1<<<(NCHAIN * NCHUNK) / 256, 256>>>(sd);
    wkv_pass2<<<NCHAIN / 256, 256>>>(sd);
    wkv_pass3<<<(NCHAIN * NCHUNK) / 256, 256>>>(sd, sf);

    // output projection: grid.x = 2 (group 0 only)
    dim3 g1(2, MM / 128);
    gemm_qkv_kernel<<<g1, 256, GS_BYTES>>>(xs, wo, wo, wo,
                                           (float*)d_out, (float*)d_out,
                                           (float*)d_out, DD, 0);
}